// round 14
// baseline (speedup 1.0000x reference)
#include <cuda_runtime.h>
#include <cuda_fp16.h>
#include <cstdint>
#include <math.h>

#define MROWS 131072        // 2048 windows * 64 tokens
#define NWIN  2048
#define D1    257
#define DIMV  256
#define KPAD  288           // 257 padded to 9 chunks of 32
#define KITERS 9
#define SCALE 0.17677669529663687f   // 32^-0.5

// ======================= scratch (device globals) ===========================
__device__ __align__(256) __half g_Ah[(size_t)MROWS * KPAD];
__device__ __align__(256) __half g_Bh[768 * KPAD];
__device__ __align__(256) __half g_BoH[256 * KPAD];
__device__ __align__(256) __half g_qvh[(size_t)MROWS * DIMV];
__device__ __align__(256) __half g_kvh[(size_t)MROWS * DIMV];
__device__ __align__(256) __half g_vvh[(size_t)MROWS * DIMV];
__device__ float g_qd[MROWS];
__device__ float g_kd[MROWS];
__device__ float g_vd[MROWS];

// ======================= PTX helpers =========================================
__device__ __forceinline__ uint32_t smem_u32(const void* p) {
    uint32_t a;
    asm("{ .reg .u64 t; cvta.to.shared.u64 t, %1; cvt.u32.u64 %0, t; }"
        : "=r"(a) : "l"(p));
    return a;
}
__device__ __forceinline__ void cp16(uint32_t s, const void* g) {
    asm volatile("cp.async.ca.shared.global [%0], [%1], 16;" :: "r"(s), "l"(g));
}
#define CP_COMMIT()  asm volatile("cp.async.commit_group;" ::: "memory")
#define CP_WAIT(n)   asm volatile("cp.async.wait_group %0;" :: "n"(n) : "memory")

#define LDSM4(r, addr) \
    asm volatile("ldmatrix.sync.aligned.m8n8.x4.shared.b16 {%0,%1,%2,%3}, [%4];" \
        : "=r"((r)[0]), "=r"((r)[1]), "=r"((r)[2]), "=r"((r)[3]) : "r"(addr))

#define LDSM2T(r, addr) \
    asm volatile("ldmatrix.sync.aligned.m8n8.x2.trans.shared.b16 {%0,%1}, [%2];" \
        : "=r"((r)[0]), "=r"((r)[1]) : "r"(addr))

#define MMA16816(c, a, b0v, b1v) \
    asm volatile("mma.sync.aligned.m16n8k16.row.col.f32.f16.f16.f32 " \
        "{%0,%1,%2,%3}, {%4,%5,%6,%7}, {%8,%9}, {%0,%1,%2,%3};" \
        : "+f"((c)[0]), "+f"((c)[1]), "+f"((c)[2]), "+f"((c)[3]) \
        : "r"((a)[0]), "r"((a)[1]), "r"((a)[2]), "r"((a)[3]), "r"(b0v), "r"(b1v))

__device__ __forceinline__ uint32_t packh2(float a, float b) {
    __half2 h = __floats2half2_rn(a, b);
    return *reinterpret_cast<uint32_t*>(&h);
}

// ============ conv_x + depth projections (warp per row) =====================
__global__ void __launch_bounds__(256) conv_x_dproj(
    const float* __restrict__ X,
    const float* __restrict__ Wq, const float* __restrict__ Wk,
    const float* __restrict__ Wv,
    __half* __restrict__ Ah,
    float* __restrict__ qd, float* __restrict__ kd, float* __restrict__ vd)
{
    const int warp = threadIdx.x >> 5;
    const int lane = threadIdx.x & 31;
    const size_t r = (size_t)blockIdx.x * 8 + warp;
    const float* xr = X + r * D1;
    float sq = 0.f, sk = 0.f, sv = 0.f;
    #pragma unroll
    for (int i = 0; i < 9; i++) {
        int c = lane + i * 32;
        float v = (c < D1) ? xr[c] : 0.f;
        Ah[r * KPAD + c] = __float2half_rn(v);
        if (c < D1) {
            sq = fmaf(v, Wq[c], sq);
            sk = fmaf(v, Wk[c], sk);
            sv = fmaf(v, Wv[c], sv);
        }
    }
    #pragma unroll
    for (int o = 16; o > 0; o >>= 1) {
        sq += __shfl_down_sync(0xffffffffu, sq, o);
        sk += __shfl_down_sync(0xffffffffu, sk, o);
        sv += __shfl_down_sync(0xffffffffu, sv, o);
    }
    if (lane == 0) { qd[r] = sq * SCALE; kd[r] = sk; vd[r] = sv; }
}

// ============ QKV weight transpose: B[n,k] = fp16(W[k, n%256]) ==============
__global__ void __launch_bounds__(256) conv_w_qkv(
    const float* __restrict__ Wqv, const float* __restrict__ Wkv,
    const float* __restrict__ Wvv, __half* __restrict__ Bh)
{
    int idx = blockIdx.x * 256 + threadIdx.x;   // 768*288 total
    int n = idx / KPAD, k = idx % KPAD;
    const float* W = (n < 256) ? Wqv : (n < 512) ? Wkv : Wvv;
    float v = (k < D1) ? W[(size_t)k * DIMV + (n & 255)] : 0.f;
    Bh[idx] = __float2half_rn(v);
}

// ============ Wout transpose: B[n,k] = fp16(Wout[k, n]) =====================
__global__ void __launch_bounds__(256) conv_w_out(
    const float* __restrict__ Wout, __half* __restrict__ Bh)
{
    int idx = blockIdx.x * 256 + threadIdx.x;   // 256*288 total
    int n = idx / KPAD, k = idx % KPAD;
    float v = (k < D1) ? Wout[(size_t)k * D1 + n] : 0.f;
    Bh[idx] = __float2half_rn(v);
}

// ============ fp16 HMMA GEMM: BM=BN=128 BK=32, 3-stage, 2x2 warps ===========
// 128 threads, 64x64 per warp: 8 LDSM4 per 32 MMAs (was 6 per 16) -> -33% LDS.
#define BM 128
#define BN 128
#define BK 32
#define SPITCH 40
#define MAT_BYTES (BM * SPITCH * 2)        // 10240
#define STAGE_BYTES (2 * MAT_BYTES)        // 20480
#define NSTAGE 3
#define GEMM_SMEM (NSTAGE * STAGE_BYTES)   // 61440

__global__ void __launch_bounds__(128, 2) gemm_mma(
    const __half* __restrict__ A, const __half* __restrict__ B,
    void* __restrict__ o0, void* __restrict__ o1, void* __restrict__ o2,
    float s0, float s1, float s2, int pitch, int half_out)
{
    extern __shared__ char sm[];
    const int tid  = threadIdx.x;
    const int lane = tid & 31;
    const int wid  = tid >> 5;
    const int wm   = wid >> 1;             // 0..1
    const int wn   = wid & 1;              // 0..1
    const int nblk = blockIdx.x;
    const size_t m0 = (size_t)blockIdx.y * BM;
    const int sel = nblk >> 1;
    void* ov = (sel == 0) ? o0 : (sel == 1) ? o1 : o2;
    const float scale = (sel == 0) ? s0 : (sel == 1) ? s1 : s2;
    const int ncol0 = (nblk & 1) * BN;
    const uint32_t sbase = smem_u32(sm);

    const __half* B_b = B + (size_t)nblk * BN * KPAD;

    // per-thread cp.async assignment (8 x 16B chunks / thread / stage)
    auto load_stage = [&](int it, int buf) {
        const int kc = it * BK;
        #pragma unroll
        for (int t = 0; t < 8; t++) {
            int id = tid + t * 128;
            int mat = id >> 9;
            int i = id & 511;
            int row = i >> 2, c = i & 3;
            const __half* g;
            if (mat == 0) g = A   + (m0 + row) * KPAD + kc + c * 8;
            else          g = B_b + (size_t)row * KPAD + kc + c * 8;
            uint32_t s = sbase + buf * STAGE_BYTES + mat * MAT_BYTES
                       + (uint32_t)(row * SPITCH + c * 8) * 2;
            cp16(s, g);
        }
        CP_COMMIT();
    };

    float acc[4][8][4];
    #pragma unroll
    for (int a = 0; a < 4; a++)
        #pragma unroll
        for (int b = 0; b < 8; b++)
            #pragma unroll
            for (int c = 0; c < 4; c++) acc[a][b][c] = 0.f;

    const uint32_t a_off = (uint32_t)((wm * 64 + (lane & 15)) * SPITCH
                                      + ((lane >> 4) << 3)) * 2;
    const uint32_t b_off = (uint32_t)((wn * 64 + ((lane >> 4) << 3) + (lane & 7)) * SPITCH
                                      + (lane & 8)) * 2;

    load_stage(0, 0);
    load_stage(1, 1);

    for (int it = 0; it < KITERS; ++it) {
        CP_WAIT(1);
        __syncthreads();
        if (it + 2 < KITERS) load_stage(it + 2, (it + 2) % NSTAGE);
        else CP_COMMIT();

        const uint32_t st = sbase + (it % NSTAGE) * STAGE_BYTES;
        const int nks = (it == KITERS - 1) ? 1 : 2;
        for (int ks = 0; ks < nks; ks++) {
            const uint32_t ko = ks * 32;
            uint32_t ah[4][4], bh[4][4];
            #pragma unroll
            for (int mi = 0; mi < 4; mi++) {
                uint32_t ao = a_off + (uint32_t)(mi * 16 * SPITCH) * 2 + ko;
                LDSM4(ah[mi], st + 0 * MAT_BYTES + ao);
            }
            #pragma unroll
            for (int nj = 0; nj < 4; nj++) {
                uint32_t bo = b_off + (uint32_t)(nj * 16 * SPITCH) * 2 + ko;
                LDSM4(bh[nj], st + 1 * MAT_BYTES + bo);
            }
            #pragma unroll
            for (int mi = 0; mi < 4; mi++)
                #pragma unroll
                for (int ni = 0; ni < 8; ni++) {
                    uint32_t b0 = bh[ni >> 1][(ni & 1) * 2];
                    uint32_t b1 = bh[ni >> 1][(ni & 1) * 2 + 1];
                    MMA16816(acc[mi][ni], ah[mi], b0, b1);
                }
        }
    }

    // ---- epilogue: warp tile 64x64 ----
    const int r0 = wm * 64 + (lane >> 2);
    const int c0 = ncol0 + wn * 64 + (lane & 3) * 2;
    if (half_out) {
        __half* o = (__half*)ov;
        #pragma unroll
        for (int mi = 0; mi < 4; mi++)
            #pragma unroll
            for (int ni = 0; ni < 8; ni++) {
                size_t row = m0 + r0 + mi * 16;
                int col = c0 + ni * 8;
                *(uint32_t*)&o[row * DIMV + col] =
                    packh2(acc[mi][ni][0] * scale, acc[mi][ni][1] * scale);
                *(uint32_t*)&o[(row + 8) * DIMV + col] =
                    packh2(acc[mi][ni][2] * scale, acc[mi][ni][3] * scale);
            }
    } else {
        float* o = (float*)ov;
        #pragma unroll
        for (int mi = 0; mi < 4; mi++)
            #pragma unroll
            for (int ni = 0; ni < 8; ni++) {
                size_t row = m0 + r0 + mi * 16;
                int col = c0 + ni * 8;
                o[row * (size_t)pitch + col]           = acc[mi][ni][0] * scale;
                o[row * (size_t)pitch + col + 1]       = acc[mi][ni][1] * scale;
                o[(row + 8) * (size_t)pitch + col]     = acc[mi][ni][2] * scale;
                o[(row + 8) * (size_t)pitch + col + 1] = acc[mi][ni][3] * scale;
            }
    }
}

// ============ fused MMA attention: 1 window/CTA, 128 thr, warp = 16 rows ====
#define APITCH 264     // halves per row (256 + 8 pad): conflict-free LDSM
#define ATTN_HALVES (3 * 64 * APITCH + 64 * 66)
#define ATTN_SMEM   (ATTN_HALVES * 2 + (64 * 3 + 260) * 4)

__global__ void __launch_bounds__(128, 2) attn_mma(
    const __half* __restrict__ qv, const __half* __restrict__ kv,
    const __half* __restrict__ vv,
    const float* __restrict__ qd, const float* __restrict__ kd,
    const float* __restrict__ vd, const float* __restrict__ Wout,
    __half* __restrict__ Ah, float* __restrict__ out)
{
    extern __shared__ char sm[];
    __half* sq    = (__half*)sm;                 // [64][APITCH]
    __half* sk    = sq + 64 * APITCH;
    __half* sv    = sk + 64 * APITCH;
    __half* sgate = sv + 64 * APITCH;            // [64][66]
    float*  s_qd  = (float*)(sm + ATTN_HALVES * 2);
    float*  s_kd  = s_qd + 64;
    float*  s_vd  = s_kd + 64;
    float*  s_w   = s_vd + 64;                   // Wout[:,256], 257 floats

    const int tid  = threadIdx.x;
    const int lane = tid & 31;
    const int wid  = tid >> 5;
    const int g    = lane >> 2;
    const int tig  = lane & 3;
    const size_t r0 = (size_t)blockIdx.x * 64;

    const uint32_t sq_u = smem_u32(sq);
    const uint32_t sk_u = smem_u32(sk);
    const uint32_t sv_u = smem_u32(sv);

    // ---- cooperative load via cp.async (fire-and-forget, one wait) ----
    {
        const uint4* gq = (const uint4*)(qv + r0 * DIMV);
        const uint4* gk = (const uint4*)(kv + r0 * DIMV);
        const uint4* gv = (const uint4*)(vv + r0 * DIMV);
        for (int i = tid; i < 2048; i += 128) {
            int row = i >> 5, c = i & 31;            // 32 x 8 halves = 256/row
            uint32_t off = (uint32_t)(row * APITCH * 2 + c * 16);
            cp16(sq_u + off, gq + i);
            cp16(sk_u + off, gk + i);
            cp16(sv_u + off, gv + i);
        }
        CP_COMMIT();
        if (tid < 64) {
            s_qd[tid] = qd[r0 + tid];
            s_kd[tid] = kd[r0 + tid];
            s_vd[tid] = vd[r0 + tid];
        }
        for (int i = tid; i < 257; i += 128)
            s_w[i] = Wout[(size_t)i * D1 + 256];
        CP_WAIT(0);
    }
    __syncthreads();

    // ---- gate table (head-invariant): sigmoid(qd_i * kd_j), fp16 ----
    for (int i = tid; i < 4096; i += 128) {
        int ii = i >> 6, jj = i & 63;
        float z = s_qd[ii] * s_kd[jj];
        sgate[ii * 66 + jj] = __float2half_rn(1.f / (1.f + __expf(-z)));
    }
    __syncthreads();

    const int mrow = wid * 16;

    float ssum[8][4];
    #pragma unroll
    for (int ni = 0; ni < 8; ni++)
        #pragma unroll
        for (int k = 0; k < 4; k++) ssum[ni][k] = 0.f;
    float ds0 = 0.f, ds1 = 0.f;

    const uint32_t a_base = sq_u + (uint32_t)((mrow + (lane & 15)) * APITCH
                                              + ((lane >> 4) << 3)) * 2;
    const uint32_t b_rowoff = (uint32_t)((((lane >> 4) << 3) + (lane & 7)) * APITCH
                                         + (lane & 8)) * 2;
    const uint32_t v_base = sv_u + (uint32_t)((lane & 15) * APITCH) * 2;

    for (int h = 0; h < 8; h++) {
        const int kb = h * 32;
        // ---- S = Q K^T (64 cols, k=32) ----
        float acc[8][4];
        #pragma unroll
        for (int ni = 0; ni < 8; ni++)
            #pragma unroll
            for (int k = 0; k < 4; k++) acc[ni][k] = 0.f;
        #pragma unroll
        for (int ks = 0; ks < 2; ks++) {
            uint32_t a[4];
            LDSM4(a, a_base + (uint32_t)(kb + ks * 16) * 2);
            #pragma unroll
            for (int nt = 0; nt < 4; nt++) {
                uint32_t b[4];
                uint32_t baddr = sk_u + b_rowoff
                               + (uint32_t)(nt * 16 * APITCH + kb + ks * 16) * 2;
                LDSM4(b, baddr);
                MMA16816(acc[nt * 2],     a, b[0], b[1]);
                MMA16816(acc[nt * 2 + 1], a, b[2], b[3]);
            }
        }
        // ---- gate + ssum + row max ----
        float m0 = -1e30f, m1 = -1e30f;
        #pragma unroll
        for (int ni = 0; ni < 8; ni++) {
            int j0 = ni * 8 + tig * 2;
            __half2 gA = *(__half2*)&sgate[(mrow + g) * 66 + j0];
            __half2 gB = *(__half2*)&sgate[(mrow + g + 8) * 66 + j0];
            float2 fA = __half22float2(gA);
            float2 fB = __half22float2(gB);
            acc[ni][0] *= fA.x;  acc[ni][1] *= fA.y;
            acc[ni][2] *= fB.x;  acc[ni][3] *= fB.y;
            ssum[ni][0] += acc[ni][0]; ssum[ni][1] += acc[ni][1];
            ssum[ni][2] += acc[ni][2]; ssum[ni][3] += acc[ni][3];
            m0 = fmaxf(m0, fmaxf(acc[ni][0], acc[ni][1]));
            m1 = fmaxf(m1, fmaxf(acc[ni][2], acc[ni][3]));
        }
        m0 = fmaxf(m0, __shfl_xor_sync(0xffffffffu, m0, 1));
        m0 = fmaxf(m0, __shfl_xor_sync(0xffffffffu, m0, 2));
        m1 = fmaxf(m1, __shfl_xor_sync(0xffffffffu, m1, 1));
        m1 = fmaxf(m1, __shfl_xor_sync(0xffffffffu, m1, 2));
        // ---- exp + row sums ----
        float sum0 = 0.f, sum1 = 0.f;
        #pragma unroll
        for (int ni = 0; ni < 8; ni++) {
            acc[ni][0] = __expf(acc[ni][0] - m0);
            acc[ni][1] = __expf(acc[ni][1] - m0);
            acc[ni][2] = __expf(acc[ni][2] - m1);
            acc[ni][3] = __expf(acc[ni][3] - m1);
            sum0 += acc[ni][0] + acc[ni][1];
            sum1 += acc[ni][2] + acc[ni][3];
        }
        sum0 += __shfl_xor_sync(0xffffffffu, sum0, 1);
        sum0 += __shfl_xor_sync(0xffffffffu, sum0, 2);
        sum1 += __shfl_xor_sync(0xffffffffu, sum1, 1);
        sum1 += __shfl_xor_sync(0xffffffffu, sum1, 2);
        const float inv0 = 1.f / sum0, inv1 = 1.f / sum1;
        // ---- P fragments directly from accumulators (FA2 identity) ----
        uint32_t pa[4][4];
        #pragma unroll
        for (int t = 0; t < 4; t++) {
            pa[t][0] = packh2(acc[2*t][0]   * inv0, acc[2*t][1]   * inv0);
            pa[t][1] = packh2(acc[2*t][2]   * inv1, acc[2*t][3]   * inv1);
            pa[t][2] = packh2(acc[2*t+1][0] * inv0, acc[2*t+1][1] * inv0);
            pa[t][3] = packh2(acc[2*t+1][2] * inv1, acc[2*t+1][3] * inv1);
        }
        // ---- out = P @ V (k=64 tokens, n=32 dims) ----
        float oacc[4][4];
        #pragma unroll
        for (int nb = 0; nb < 4; nb++)
            #pragma unroll
            for (int k = 0; k < 4; k++) oacc[nb][k] = 0.f;
        #pragma unroll
        for (int t = 0; t < 4; t++) {
            #pragma unroll
            for (int nb = 0; nb < 4; nb++) {
                uint32_t b2[2];
                uint32_t vaddr = v_base
                               + (uint32_t)(t * 16 * APITCH + kb + nb * 8) * 2;
                LDSM2T(b2, vaddr);
                MMA16816(oacc[nb], pa[t], b2[0], b2[1]);
            }
        }
        // ---- write ov (fp16 into A matrix) + out[:,256] dot partials ----
        #pragma unroll
        for (int nb = 0; nb < 4; nb++) {
            int c0 = kb + nb * 8 + tig * 2;
            float w0 = s_w[c0], w1 = s_w[c0 + 1];
            ds0 += oacc[nb][0] * w0 + oacc[nb][1] * w1;
            ds1 += oacc[nb][2] * w0 + oacc[nb][3] * w1;
            *(uint32_t*)&Ah[(r0 + mrow + g) * KPAD + c0] =
                packh2(oacc[nb][0], oacc[nb][1]);
            *(uint32_t*)&Ah[(r0 + mrow + g + 8) * KPAD + c0] =
                packh2(oacc[nb][2], oacc[nb][3]);
        }
    }

    // ---- depth attention: softmax(ssum) . vd  (all in registers) ----
    float m0 = -1e30f, m1 = -1e30f;
    #pragma unroll
    for (int ni = 0; ni < 8; ni++) {
        m0 = fmaxf(m0, fmaxf(ssum[ni][0], ssum[ni][1]));
        m1 = fmaxf(m1, fmaxf(ssum[ni][2], ssum[ni][3]));
    }
    m0 = fmaxf(m0, __shfl_xor_sync(0xffffffffu, m0, 1));
    m0 = fmaxf(m0, __shfl_xor_sync(0xffffffffu, m0, 2));
    m1 = fmaxf(m1, __shfl_xor_sync(0xffffffffu, m1, 1));
    m1 = fmaxf(m1, __shfl_xor_sync(0xffffffffu, m1, 2));
    float se0 = 0.f, se1 = 0.f, av0 = 0.f, av1 = 0.f;
    #pragma unroll
    for (int ni = 0; ni < 8; ni++) {
        int j0 = ni * 8 + tig * 2;
        float v0 = s_vd[j0], v1 = s_vd[j0 + 1];
        float e0 = __expf(ssum[ni][0] - m0);
        float e1 = __expf(ssum[ni][1] - m0);
        float e2 = __expf(ssum[ni][2] - m1);
        float e3 = __expf(ssum[ni][3] - m1);
        se0 += e0 + e1;  av0 += e0 * v0 + e1 * v1;
        se1 += e2 + e3;  av1 += e2 * v0 + e3 * v1;
    }
    se0 += __shfl_xor_sync(0xffffffffu, se0, 1);
    se0 += __shfl_xor_sync(0xffffffffu, se0, 2);
    av0 += __shfl_xor_sync(0xffffffffu, av0, 1);
    av0 += __shfl_xor_sync(0xffffffffu, av0, 2);
    se1 += __shfl_xor_sync(0xffffffffu, se1, 1);
    se1 += __shfl_xor_sync(0xffffffffu, se1, 2);
    av1 += __shfl_xor_sync(0xffffffffu, av1, 1);
    av1 += __shfl_xor_sync(0xffffffffu, av1, 2);
    ds0 += __shfl_xor_sync(0xffffffffu, ds0, 1);
    ds0 += __shfl_xor_sync(0xffffffffu, ds0, 2);
    ds1 += __shfl_xor_sync(0xffffffffu, ds1, 1);
    ds1 += __shfl_xor_sync(0xffffffffu, ds1, 2);

    if (tig == 0) {
        float od0 = av0 / se0, od1 = av1 / se1;
        size_t ra = r0 + mrow + g, rb = ra + 8;
        Ah[ra * KPAD + 256] = __float2half_rn(od0);
        Ah[rb * KPAD + 256] = __float2half_rn(od1);
        out[ra * D1 + 256] = ds0 + od0 * s_w[256];
        out[rb * D1 + 256] = ds1 + od1 * s_w[256];
    }
}

// ---------------- launch -----------------------------------------------------
extern "C" void kernel_launch(void* const* d_in, const int* in_sizes, int n_in,
                              void* d_out, int out_size)
{
    const float* x    = (const float*)d_in[0];
    const float* Wqv  = (const float*)d_in[1];
    const float* Wkv  = (const float*)d_in[2];
    const float* Wvv  = (const float*)d_in[3];
    const float* Wqd  = (const float*)d_in[4];
    const float* Wkd  = (const float*)d_in[5];
    const float* Wvd  = (const float*)d_in[6];
    const float* Wout = (const float*)d_in[7];
    float* out = (float*)d_out;

    __half *Ah, *Bh, *BoH, *qvh, *kvh, *vvh;
    float *qd, *kd, *vd;
    cudaGetSymbolAddress((void**)&Ah,  g_Ah);
    cudaGetSymbolAddress((void**)&Bh,  g_Bh);
    cudaGetSymbolAddress((void**)&BoH, g_BoH);
    cudaGetSymbolAddress((void**)&qvh, g_qvh);
    cudaGetSymbolAddress((void**)&kvh, g_kvh);
    cudaGetSymbolAddress((void**)&vvh, g_vvh);
    cudaGetSymbolAddress((void**)&qd,  g_qd);
    cudaGetSymbolAddress((void**)&kd,  g_kd);
    cudaGetSymbolAddress((void**)&vd,  g_vd);

    cudaFuncSetAttribute(gemm_mma,
                         cudaFuncAttributeMaxDynamicSharedMemorySize, GEMM_SMEM);
    cudaFuncSetAttribute(attn_mma,
                         cudaFuncAttributeMaxDynamicSharedMemorySize, ATTN_SMEM);

    conv_w_qkv<<<768 * KPAD / 256, 256>>>(Wqv, Wkv, Wvv, Bh);
    conv_w_out<<<256 * KPAD / 256, 256>>>(Wout, BoH);
    conv_x_dproj<<<MROWS / 8, 256>>>(x, Wqd, Wkd, Wvd, Ah, qd, kd, vd);

    gemm_mma<<<dim3(6, MROWS / BM), 128, GEMM_SMEM>>>(
        Ah, Bh, qvh, kvh, vvh, SCALE, 1.f, 1.f, DIMV, 1);

    attn_mma<<<NWIN, 128, ATTN_SMEM>>>(qvh, kvh, vvh, qd, kd, vd, Wout, Ah, out);

    gemm_mma<<<dim3(2, MROWS / BM), 128, GEMM_SMEM>>>(
        Ah, BoH, out, out, out, 1.f, 1.f, 1.f, D1, 0);
}

// round 15
// speedup vs baseline: 1.0003x; 1.0003x over previous
#include <cuda_runtime.h>
#include <cuda_fp16.h>
#include <cstdint>
#include <math.h>

#define MROWS 131072        // 2048 windows * 64 tokens
#define NWIN  2048
#define D1    257
#define DIMV  256
#define KPAD  288           // 257 padded to 9 chunks of 32
#define KITERS 9
#define SCALE 0.17677669529663687f   // 32^-0.5

// ======================= scratch (device globals) ===========================
__device__ __align__(256) __half g_Ah[(size_t)MROWS * KPAD];
__device__ __align__(256) __half g_Bh[768 * KPAD];
__device__ __align__(256) __half g_BoH[256 * KPAD];
__device__ __align__(256) __half g_qvh[(size_t)MROWS * DIMV];
__device__ __align__(256) __half g_kvh[(size_t)MROWS * DIMV];
__device__ __align__(256) __half g_vvh[(size_t)MROWS * DIMV];
__device__ float g_qd[MROWS];
__device__ float g_kd[MROWS];
__device__ float g_vd[MROWS];

// ======================= PTX helpers =========================================
__device__ __forceinline__ uint32_t smem_u32(const void* p) {
    uint32_t a;
    asm("{ .reg .u64 t; cvta.to.shared.u64 t, %1; cvt.u32.u64 %0, t; }"
        : "=r"(a) : "l"(p));
    return a;
}
__device__ __forceinline__ void cp16(uint32_t s, const void* g) {
    asm volatile("cp.async.ca.shared.global [%0], [%1], 16;" :: "r"(s), "l"(g));
}
#define CP_COMMIT()  asm volatile("cp.async.commit_group;" ::: "memory")
#define CP_WAIT(n)   asm volatile("cp.async.wait_group %0;" :: "n"(n) : "memory")

#define LDSM4(r, addr) \
    asm volatile("ldmatrix.sync.aligned.m8n8.x4.shared.b16 {%0,%1,%2,%3}, [%4];" \
        : "=r"((r)[0]), "=r"((r)[1]), "=r"((r)[2]), "=r"((r)[3]) : "r"(addr))

#define LDSM2T(r, addr) \
    asm volatile("ldmatrix.sync.aligned.m8n8.x2.trans.shared.b16 {%0,%1}, [%2];" \
        : "=r"((r)[0]), "=r"((r)[1]) : "r"(addr))

#define MMA16816(c, a, b0v, b1v) \
    asm volatile("mma.sync.aligned.m16n8k16.row.col.f32.f16.f16.f32 " \
        "{%0,%1,%2,%3}, {%4,%5,%6,%7}, {%8,%9}, {%0,%1,%2,%3};" \
        : "+f"((c)[0]), "+f"((c)[1]), "+f"((c)[2]), "+f"((c)[3]) \
        : "r"((a)[0]), "r"((a)[1]), "r"((a)[2]), "r"((a)[3]), "r"(b0v), "r"(b1v))

__device__ __forceinline__ uint32_t packh2(float a, float b) {
    __half2 h = __floats2half2_rn(a, b);
    return *reinterpret_cast<uint32_t*>(&h);
}

// ============ conv_x + depth projections (warp per row) =====================
__global__ void __launch_bounds__(256) conv_x_dproj(
    const float* __restrict__ X,
    const float* __restrict__ Wq, const float* __restrict__ Wk,
    const float* __restrict__ Wv,
    __half* __restrict__ Ah,
    float* __restrict__ qd, float* __restrict__ kd, float* __restrict__ vd)
{
    const int warp = threadIdx.x >> 5;
    const int lane = threadIdx.x & 31;
    const size_t r = (size_t)blockIdx.x * 8 + warp;
    const float* xr = X + r * D1;
    float sq = 0.f, sk = 0.f, sv = 0.f;
    #pragma unroll
    for (int i = 0; i < 9; i++) {
        int c = lane + i * 32;
        float v = (c < D1) ? xr[c] : 0.f;
        Ah[r * KPAD + c] = __float2half_rn(v);
        if (c < D1) {
            sq = fmaf(v, Wq[c], sq);
            sk = fmaf(v, Wk[c], sk);
            sv = fmaf(v, Wv[c], sv);
        }
    }
    #pragma unroll
    for (int o = 16; o > 0; o >>= 1) {
        sq += __shfl_down_sync(0xffffffffu, sq, o);
        sk += __shfl_down_sync(0xffffffffu, sk, o);
        sv += __shfl_down_sync(0xffffffffu, sv, o);
    }
    if (lane == 0) { qd[r] = sq * SCALE; kd[r] = sk; vd[r] = sv; }
}

// ============ QKV weight transpose: B[n,k] = fp16(W[k, n%256]) ==============
__global__ void __launch_bounds__(256) conv_w_qkv(
    const float* __restrict__ Wqv, const float* __restrict__ Wkv,
    const float* __restrict__ Wvv, __half* __restrict__ Bh)
{
    int idx = blockIdx.x * 256 + threadIdx.x;   // 768*288 total
    int n = idx / KPAD, k = idx % KPAD;
    const float* W = (n < 256) ? Wqv : (n < 512) ? Wkv : Wvv;
    float v = (k < D1) ? W[(size_t)k * DIMV + (n & 255)] : 0.f;
    Bh[idx] = __float2half_rn(v);
}

// ============ Wout transpose: B[n,k] = fp16(Wout[k, n]) =====================
__global__ void __launch_bounds__(256) conv_w_out(
    const float* __restrict__ Wout, __half* __restrict__ Bh)
{
    int idx = blockIdx.x * 256 + threadIdx.x;   // 256*288 total
    int n = idx / KPAD, k = idx % KPAD;
    float v = (k < D1) ? Wout[(size_t)k * D1 + n] : 0.f;
    Bh[idx] = __float2half_rn(v);
}

// ============ fp16 HMMA GEMM: BM=BN=128 BK=32, 3-stage, 2x2 warps ===========
// 128 threads, 64x64 per warp: 8 LDSM4 per 32 MMAs (was 6 per 16) -> -33% LDS.
#define BM 128
#define BN 128
#define BK 32
#define SPITCH 40
#define MAT_BYTES (BM * SPITCH * 2)        // 10240
#define STAGE_BYTES (2 * MAT_BYTES)        // 20480
#define NSTAGE 3
#define GEMM_SMEM (NSTAGE * STAGE_BYTES)   // 61440

__global__ void __launch_bounds__(128, 2) gemm_mma(
    const __half* __restrict__ A, const __half* __restrict__ B,
    void* __restrict__ o0, void* __restrict__ o1, void* __restrict__ o2,
    float s0, float s1, float s2, int pitch, int half_out)
{
    extern __shared__ char sm[];
    const int tid  = threadIdx.x;
    const int lane = tid & 31;
    const int wid  = tid >> 5;
    const int wm   = wid >> 1;             // 0..1
    const int wn   = wid & 1;              // 0..1
    const int nblk = blockIdx.x;
    const size_t m0 = (size_t)blockIdx.y * BM;
    const int sel = nblk >> 1;
    void* ov = (sel == 0) ? o0 : (sel == 1) ? o1 : o2;
    const float scale = (sel == 0) ? s0 : (sel == 1) ? s1 : s2;
    const int ncol0 = (nblk & 1) * BN;
    const uint32_t sbase = smem_u32(sm);

    const __half* B_b = B + (size_t)nblk * BN * KPAD;

    // per-thread cp.async assignment (8 x 16B chunks / thread / stage)
    auto load_stage = [&](int it, int buf) {
        const int kc = it * BK;
        #pragma unroll
        for (int t = 0; t < 8; t++) {
            int id = tid + t * 128;
            int mat = id >> 9;
            int i = id & 511;
            int row = i >> 2, c = i & 3;
            const __half* g;
            if (mat == 0) g = A   + (m0 + row) * KPAD + kc + c * 8;
            else          g = B_b + (size_t)row * KPAD + kc + c * 8;
            uint32_t s = sbase + buf * STAGE_BYTES + mat * MAT_BYTES
                       + (uint32_t)(row * SPITCH + c * 8) * 2;
            cp16(s, g);
        }
        CP_COMMIT();
    };

    float acc[4][8][4];
    #pragma unroll
    for (int a = 0; a < 4; a++)
        #pragma unroll
        for (int b = 0; b < 8; b++)
            #pragma unroll
            for (int c = 0; c < 4; c++) acc[a][b][c] = 0.f;

    const uint32_t a_off = (uint32_t)((wm * 64 + (lane & 15)) * SPITCH
                                      + ((lane >> 4) << 3)) * 2;
    const uint32_t b_off = (uint32_t)((wn * 64 + ((lane >> 4) << 3) + (lane & 7)) * SPITCH
                                      + (lane & 8)) * 2;

    load_stage(0, 0);
    load_stage(1, 1);

    for (int it = 0; it < KITERS; ++it) {
        CP_WAIT(1);
        __syncthreads();
        if (it + 2 < KITERS) load_stage(it + 2, (it + 2) % NSTAGE);
        else CP_COMMIT();

        const uint32_t st = sbase + (it % NSTAGE) * STAGE_BYTES;
        const int nks = (it == KITERS - 1) ? 1 : 2;
        for (int ks = 0; ks < nks; ks++) {
            const uint32_t ko = ks * 32;
            uint32_t ah[4][4], bh[4][4];
            #pragma unroll
            for (int mi = 0; mi < 4; mi++) {
                uint32_t ao = a_off + (uint32_t)(mi * 16 * SPITCH) * 2 + ko;
                LDSM4(ah[mi], st + 0 * MAT_BYTES + ao);
            }
            #pragma unroll
            for (int nj = 0; nj < 4; nj++) {
                uint32_t bo = b_off + (uint32_t)(nj * 16 * SPITCH) * 2 + ko;
                LDSM4(bh[nj], st + 1 * MAT_BYTES + bo);
            }
            #pragma unroll
            for (int mi = 0; mi < 4; mi++)
                #pragma unroll
                for (int ni = 0; ni < 8; ni++) {
                    uint32_t b0 = bh[ni >> 1][(ni & 1) * 2];
                    uint32_t b1 = bh[ni >> 1][(ni & 1) * 2 + 1];
                    MMA16816(acc[mi][ni], ah[mi], b0, b1);
                }
        }
    }

    // ---- epilogue: warp tile 64x64 ----
    const int r0 = wm * 64 + (lane >> 2);
    const int c0 = ncol0 + wn * 64 + (lane & 3) * 2;
    if (half_out) {
        __half* o = (__half*)ov;
        #pragma unroll
        for (int mi = 0; mi < 4; mi++)
            #pragma unroll
            for (int ni = 0; ni < 8; ni++) {
                size_t row = m0 + r0 + mi * 16;
                int col = c0 + ni * 8;
                *(uint32_t*)&o[row * DIMV + col] =
                    packh2(acc[mi][ni][0] * scale, acc[mi][ni][1] * scale);
                *(uint32_t*)&o[(row + 8) * DIMV + col] =
                    packh2(acc[mi][ni][2] * scale, acc[mi][ni][3] * scale);
            }
    } else {
        float* o = (float*)ov;
        #pragma unroll
        for (int mi = 0; mi < 4; mi++)
            #pragma unroll
            for (int ni = 0; ni < 8; ni++) {
                size_t row = m0 + r0 + mi * 16;
                int col = c0 + ni * 8;
                o[row * (size_t)pitch + col]           = acc[mi][ni][0] * scale;
                o[row * (size_t)pitch + col + 1]       = acc[mi][ni][1] * scale;
                o[(row + 8) * (size_t)pitch + col]     = acc[mi][ni][2] * scale;
                o[(row + 8) * (size_t)pitch + col + 1] = acc[mi][ni][3] * scale;
            }
    }
}

// ============ fused MMA attention: 1 window/CTA, 128 thr, warp = 16 rows ====
#define APITCH 264     // halves per row (256 + 8 pad): conflict-free LDSM
#define ATTN_HALVES (3 * 64 * APITCH + 64 * 66)
#define ATTN_SMEM   (ATTN_HALVES * 2 + (64 * 3 + 260) * 4)

__global__ void __launch_bounds__(128, 2) attn_mma(
    const __half* __restrict__ qv, const __half* __restrict__ kv,
    const __half* __restrict__ vv,
    const float* __restrict__ qd, const float* __restrict__ kd,
    const float* __restrict__ vd, const float* __restrict__ Wout,
    __half* __restrict__ Ah, float* __restrict__ out)
{
    extern __shared__ char sm[];
    __half* sq    = (__half*)sm;                 // [64][APITCH]
    __half* sk    = sq + 64 * APITCH;
    __half* sv    = sk + 64 * APITCH;
    __half* sgate = sv + 64 * APITCH;            // [64][66]
    float*  s_qd  = (float*)(sm + ATTN_HALVES * 2);
    float*  s_kd  = s_qd + 64;
    float*  s_vd  = s_kd + 64;
    float*  s_w   = s_vd + 64;                   // Wout[:,256], 257 floats

    const int tid  = threadIdx.x;
    const int lane = tid & 31;
    const int wid  = tid >> 5;
    const int g    = lane >> 2;
    const int tig  = lane & 3;
    const size_t r0 = (size_t)blockIdx.x * 64;

    const uint32_t sq_u = smem_u32(sq);
    const uint32_t sk_u = smem_u32(sk);
    const uint32_t sv_u = smem_u32(sv);

    // ---- cooperative load via cp.async (fire-and-forget, one wait) ----
    {
        const uint4* gq = (const uint4*)(qv + r0 * DIMV);
        const uint4* gk = (const uint4*)(kv + r0 * DIMV);
        const uint4* gv = (const uint4*)(vv + r0 * DIMV);
        for (int i = tid; i < 2048; i += 128) {
            int row = i >> 5, c = i & 31;            // 32 x 8 halves = 256/row
            uint32_t off = (uint32_t)(row * APITCH * 2 + c * 16);
            cp16(sq_u + off, gq + i);
            cp16(sk_u + off, gk + i);
            cp16(sv_u + off, gv + i);
        }
        CP_COMMIT();
        if (tid < 64) {
            s_qd[tid] = qd[r0 + tid];
            s_kd[tid] = kd[r0 + tid];
            s_vd[tid] = vd[r0 + tid];
        }
        for (int i = tid; i < 257; i += 128)
            s_w[i] = Wout[(size_t)i * D1 + 256];
        CP_WAIT(0);
    }
    __syncthreads();

    // ---- gate table (head-invariant): sigmoid(qd_i * kd_j), fp16 ----
    for (int i = tid; i < 4096; i += 128) {
        int ii = i >> 6, jj = i & 63;
        float z = s_qd[ii] * s_kd[jj];
        sgate[ii * 66 + jj] = __float2half_rn(1.f / (1.f + __expf(-z)));
    }
    __syncthreads();

    const int mrow = wid * 16;

    float ssum[8][4];
    #pragma unroll
    for (int ni = 0; ni < 8; ni++)
        #pragma unroll
        for (int k = 0; k < 4; k++) ssum[ni][k] = 0.f;
    float ds0 = 0.f, ds1 = 0.f;

    const uint32_t a_base = sq_u + (uint32_t)((mrow + (lane & 15)) * APITCH
                                              + ((lane >> 4) << 3)) * 2;
    const uint32_t b_rowoff = (uint32_t)((((lane >> 4) << 3) + (lane & 7)) * APITCH
                                         + (lane & 8)) * 2;
    const uint32_t v_base = sv_u + (uint32_t)((lane & 15) * APITCH) * 2;

    for (int h = 0; h < 8; h++) {
        const int kb = h * 32;
        // ---- S = Q K^T (64 cols, k=32) ----
        float acc[8][4];
        #pragma unroll
        for (int ni = 0; ni < 8; ni++)
            #pragma unroll
            for (int k = 0; k < 4; k++) acc[ni][k] = 0.f;
        #pragma unroll
        for (int ks = 0; ks < 2; ks++) {
            uint32_t a[4];
            LDSM4(a, a_base + (uint32_t)(kb + ks * 16) * 2);
            #pragma unroll
            for (int nt = 0; nt < 4; nt++) {
                uint32_t b[4];
                uint32_t baddr = sk_u + b_rowoff
                               + (uint32_t)(nt * 16 * APITCH + kb + ks * 16) * 2;
                LDSM4(b, baddr);
                MMA16816(acc[nt * 2],     a, b[0], b[1]);
                MMA16816(acc[nt * 2 + 1], a, b[2], b[3]);
            }
        }
        // ---- gate + ssum + row max ----
        float m0 = -1e30f, m1 = -1e30f;
        #pragma unroll
        for (int ni = 0; ni < 8; ni++) {
            int j0 = ni * 8 + tig * 2;
            __half2 gA = *(__half2*)&sgate[(mrow + g) * 66 + j0];
            __half2 gB = *(__half2*)&sgate[(mrow + g + 8) * 66 + j0];
            float2 fA = __half22float2(gA);
            float2 fB = __half22float2(gB);
            acc[ni][0] *= fA.x;  acc[ni][1] *= fA.y;
            acc[ni][2] *= fB.x;  acc[ni][3] *= fB.y;
            ssum[ni][0] += acc[ni][0]; ssum[ni][1] += acc[ni][1];
            ssum[ni][2] += acc[ni][2]; ssum[ni][3] += acc[ni][3];
            m0 = fmaxf(m0, fmaxf(acc[ni][0], acc[ni][1]));
            m1 = fmaxf(m1, fmaxf(acc[ni][2], acc[ni][3]));
        }
        m0 = fmaxf(m0, __shfl_xor_sync(0xffffffffu, m0, 1));
        m0 = fmaxf(m0, __shfl_xor_sync(0xffffffffu, m0, 2));
        m1 = fmaxf(m1, __shfl_xor_sync(0xffffffffu, m1, 1));
        m1 = fmaxf(m1, __shfl_xor_sync(0xffffffffu, m1, 2));
        // ---- exp + row sums ----
        float sum0 = 0.f, sum1 = 0.f;
        #pragma unroll
        for (int ni = 0; ni < 8; ni++) {
            acc[ni][0] = __expf(acc[ni][0] - m0);
            acc[ni][1] = __expf(acc[ni][1] - m0);
            acc[ni][2] = __expf(acc[ni][2] - m1);
            acc[ni][3] = __expf(acc[ni][3] - m1);
            sum0 += acc[ni][0] + acc[ni][1];
            sum1 += acc[ni][2] + acc[ni][3];
        }
        sum0 += __shfl_xor_sync(0xffffffffu, sum0, 1);
        sum0 += __shfl_xor_sync(0xffffffffu, sum0, 2);
        sum1 += __shfl_xor_sync(0xffffffffu, sum1, 1);
        sum1 += __shfl_xor_sync(0xffffffffu, sum1, 2);
        const float inv0 = 1.f / sum0, inv1 = 1.f / sum1;
        // ---- P fragments directly from accumulators (FA2 identity) ----
        uint32_t pa[4][4];
        #pragma unroll
        for (int t = 0; t < 4; t++) {
            pa[t][0] = packh2(acc[2*t][0]   * inv0, acc[2*t][1]   * inv0);
            pa[t][1] = packh2(acc[2*t][2]   * inv1, acc[2*t][3]   * inv1);
            pa[t][2] = packh2(acc[2*t+1][0] * inv0, acc[2*t+1][1] * inv0);
            pa[t][3] = packh2(acc[2*t+1][2] * inv1, acc[2*t+1][3] * inv1);
        }
        // ---- out = P @ V (k=64 tokens, n=32 dims) ----
        float oacc[4][4];
        #pragma unroll
        for (int nb = 0; nb < 4; nb++)
            #pragma unroll
            for (int k = 0; k < 4; k++) oacc[nb][k] = 0.f;
        #pragma unroll
        for (int t = 0; t < 4; t++) {
            #pragma unroll
            for (int nb = 0; nb < 4; nb++) {
                uint32_t b2[2];
                uint32_t vaddr = v_base
                               + (uint32_t)(t * 16 * APITCH + kb + nb * 8) * 2;
                LDSM2T(b2, vaddr);
                MMA16816(oacc[nb], pa[t], b2[0], b2[1]);
            }
        }
        // ---- write ov (fp16 into A matrix) + out[:,256] dot partials ----
        #pragma unroll
        for (int nb = 0; nb < 4; nb++) {
            int c0 = kb + nb * 8 + tig * 2;
            float w0 = s_w[c0], w1 = s_w[c0 + 1];
            ds0 += oacc[nb][0] * w0 + oacc[nb][1] * w1;
            ds1 += oacc[nb][2] * w0 + oacc[nb][3] * w1;
            *(uint32_t*)&Ah[(r0 + mrow + g) * KPAD + c0] =
                packh2(oacc[nb][0], oacc[nb][1]);
            *(uint32_t*)&Ah[(r0 + mrow + g + 8) * KPAD + c0] =
                packh2(oacc[nb][2], oacc[nb][3]);
        }
    }

    // ---- depth attention: softmax(ssum) . vd  (all in registers) ----
    float m0 = -1e30f, m1 = -1e30f;
    #pragma unroll
    for (int ni = 0; ni < 8; ni++) {
        m0 = fmaxf(m0, fmaxf(ssum[ni][0], ssum[ni][1]));
        m1 = fmaxf(m1, fmaxf(ssum[ni][2], ssum[ni][3]));
    }
    m0 = fmaxf(m0, __shfl_xor_sync(0xffffffffu, m0, 1));
    m0 = fmaxf(m0, __shfl_xor_sync(0xffffffffu, m0, 2));
    m1 = fmaxf(m1, __shfl_xor_sync(0xffffffffu, m1, 1));
    m1 = fmaxf(m1, __shfl_xor_sync(0xffffffffu, m1, 2));
    float se0 = 0.f, se1 = 0.f, av0 = 0.f, av1 = 0.f;
    #pragma unroll
    for (int ni = 0; ni < 8; ni++) {
        int j0 = ni * 8 + tig * 2;
        float v0 = s_vd[j0], v1 = s_vd[j0 + 1];
        float e0 = __expf(ssum[ni][0] - m0);
        float e1 = __expf(ssum[ni][1] - m0);
        float e2 = __expf(ssum[ni][2] - m1);
        float e3 = __expf(ssum[ni][3] - m1);
        se0 += e0 + e1;  av0 += e0 * v0 + e1 * v1;
        se1 += e2 + e3;  av1 += e2 * v0 + e3 * v1;
    }
    se0 += __shfl_xor_sync(0xffffffffu, se0, 1);
    se0 += __shfl_xor_sync(0xffffffffu, se0, 2);
    av0 += __shfl_xor_sync(0xffffffffu, av0, 1);
    av0 += __shfl_xor_sync(0xffffffffu, av0, 2);
    se1 += __shfl_xor_sync(0xffffffffu, se1, 1);
    se1 += __shfl_xor_sync(0xffffffffu, se1, 2);
    av1 += __shfl_xor_sync(0xffffffffu, av1, 1);
    av1 += __shfl_xor_sync(0xffffffffu, av1, 2);
    ds0 += __shfl_xor_sync(0xffffffffu, ds0, 1);
    ds0 += __shfl_xor_sync(0xffffffffu, ds0, 2);
    ds1 += __shfl_xor_sync(0xffffffffu, ds1, 1);
    ds1 += __shfl_xor_sync(0xffffffffu, ds1, 2);

    if (tig == 0) {
        float od0 = av0 / se0, od1 = av1 / se1;
        size_t ra = r0 + mrow + g, rb = ra + 8;
        Ah[ra * KPAD + 256] = __float2half_rn(od0);
        Ah[rb * KPAD + 256] = __float2half_rn(od1);
        out[ra * D1 + 256] = ds0 + od0 * s_w[256];
        out[rb * D1 + 256] = ds1 + od1 * s_w[256];
    }
}

// ---------------- launch -----------------------------------------------------
extern "C" void kernel_launch(void* const* d_in, const int* in_sizes, int n_in,
                              void* d_out, int out_size)
{
    const float* x    = (const float*)d_in[0];
    const float* Wqv  = (const float*)d_in[1];
    const float* Wkv  = (const float*)d_in[2];
    const float* Wvv  = (const float*)d_in[3];
    const float* Wqd  = (const float*)d_in[4];
    const float* Wkd  = (const float*)d_in[5];
    const float* Wvd  = (const float*)d_in[6];
    const float* Wout = (const float*)d_in[7];
    float* out = (float*)d_out;

    __half *Ah, *Bh, *BoH, *qvh, *kvh, *vvh;
    float *qd, *kd, *vd;
    cudaGetSymbolAddress((void**)&Ah,  g_Ah);
    cudaGetSymbolAddress((void**)&Bh,  g_Bh);
    cudaGetSymbolAddress((void**)&BoH, g_BoH);
    cudaGetSymbolAddress((void**)&qvh, g_qvh);
    cudaGetSymbolAddress((void**)&kvh, g_kvh);
    cudaGetSymbolAddress((void**)&vvh, g_vvh);
    cudaGetSymbolAddress((void**)&qd,  g_qd);
    cudaGetSymbolAddress((void**)&kd,  g_kd);
    cudaGetSymbolAddress((void**)&vd,  g_vd);

    cudaFuncSetAttribute(gemm_mma,
                         cudaFuncAttributeMaxDynamicSharedMemorySize, GEMM_SMEM);
    cudaFuncSetAttribute(attn_mma,
                         cudaFuncAttributeMaxDynamicSharedMemorySize, ATTN_SMEM);

    conv_w_qkv<<<768 * KPAD / 256, 256>>>(Wqv, Wkv, Wvv, Bh);
    conv_w_out<<<256 * KPAD / 256, 256>>>(Wout, BoH);
    conv_x_dproj<<<MROWS / 8, 256>>>(x, Wqd, Wkd, Wvd, Ah, qd, kd, vd);

    gemm_mma<<<dim3(6, MROWS / BM), 128, GEMM_SMEM>>>(
        Ah, Bh, qvh, kvh, vvh, SCALE, 1.f, 1.f, DIMV, 1);

    attn_mma<<<NWIN, 128, ATTN_SMEM>>>(qvh, kvh, vvh, qd, kd, vd, Wout, Ah, out);

    gemm_mma<<<dim3(2, MROWS / BM), 128, GEMM_SMEM>>>(
        Ah, BoH, out, out, out, 1.f, 1.f, 1.f, D1, 0);
}